// round 16
// baseline (speedup 1.0000x reference)
#include <cuda_runtime.h>
#include <cuda_fp16.h>
#include <cstdint>

#define BATCH 8192
#define TMAX  (BATCH * 63)
typedef unsigned long long ull;

__device__ int      g_off[BATCH + 1];
__device__ unsigned g_Pi[BATCH * 384];            // ordered-uint per-(seg,col) max
__device__ __align__(16) int2 g_meta[TMAX];       // per token: {segment id, segment end}

union F2U { ull u; float2 f; };
__device__ __forceinline__ void fma2(ull& a, ull x, ull w) {
    asm("fma.rn.f32x2 %0, %1, %2, %0;" : "+l"(a) : "l"(x), "l"(w));
}
__device__ __forceinline__ unsigned fkey(float f) {
    unsigned b = __float_as_uint(f);
    return (b & 0x80000000u) ? ~b : (b | 0x80000000u);
}
__device__ __forceinline__ float fdec(unsigned k) {
    unsigned b = (k & 0x80000000u) ? (k ^ 0x80000000u) : ~k;
    return __uint_as_float(b);
}
// pack two f32 -> f16x2 (lo = first element)
__device__ __forceinline__ uint32_t pkh(float lo, float hi) {
    uint32_t r;
    asm("cvt.rn.f16x2.f32 %0, %1, %2;" : "=r"(r) : "f"(hi), "f"(lo));
    return r;
}
__device__ __forceinline__ uint32_t hmax2(uint32_t a, uint32_t b) {
    uint32_t r; asm("max.f16x2 %0, %1, %2;" : "=r"(r) : "r"(a), "r"(b)); return r;
}
__device__ __forceinline__ float2 h2f2(uint32_t v) {
    __half2 h = *reinterpret_cast<__half2*>(&v);
    return __half22float2(h);
}
// m16n8k16 fp16 HMMA, fp32 accumulate (sm_80+ baseline PTX)
__device__ __forceinline__ void mma16(float* d, const uint32_t* a, uint32_t b0, uint32_t b1) {
    asm volatile(
        "mma.sync.aligned.m16n8k16.row.col.f32.f16.f16.f32 "
        "{%0,%1,%2,%3}, {%4,%5,%6,%7}, {%8,%9}, {%0,%1,%2,%3};"
        : "+f"(d[0]), "+f"(d[1]), "+f"(d[2]), "+f"(d[3])
        : "r"(a[0]), "r"(a[1]), "r"(a[2]), "r"(a[3]), "r"(b0), "r"(b1));
}

// ---------------- small setup kernels ----------------
__global__ void k_init() {
    int i = blockIdx.x * blockDim.x + threadIdx.x;
    if (i < BATCH * 384) g_Pi[i] = 0u;
}
__global__ void k_scan(const int* __restrict__ sizes) {
    __shared__ int part[1024];
    int tid = threadIdx.x;
    int base = tid * 8;
    int pref[8];
    int s = 0;
#pragma unroll
    for (int r = 0; r < 8; r++) { pref[r] = s; s += sizes[base + r]; }
    part[tid] = s;
    __syncthreads();
    for (int off = 1; off < 1024; off <<= 1) {
        int v = (tid >= off) ? part[tid - off] : 0;
        __syncthreads();
        part[tid] += v;
        __syncthreads();
    }
    int excl = (tid > 0) ? part[tid - 1] : 0;
#pragma unroll
    for (int r = 0; r < 8; r++) g_off[base + r] = excl + pref[r];
    if (tid == 1023) g_off[BATCH] = part[1023];
}
__global__ void k_prep() {
    int s = blockIdx.x * blockDim.x + threadIdx.x;
    if (s >= BATCH) return;
    int a = g_off[s], e = g_off[s + 1];
    int2 v = make_int2(s, e);
    for (int r = a; r < e; r++) g_meta[r] = v;
}

// ---------------- fp16 HMMA conv, ping-pong group pipeline ----------------
// Dense stream, tap shift folded into the GEMM. 512 threads = 2 groups of 8
// warps alternating roles by tile parity: group p%2 does MMA(tile p) from
// xbuf[p%2] then transposes D (packed f16x2) into dbuf[p%2]; the OTHER group
// concurrently epilogues tile p-1 from dbuf[(p-1)%2] (SIMD max.f16x2
// segmented max + ordered-uint atomicMax) and stages tile p+1 (LDG f32 ->
// pkh -> STS f16x2) into xbuf[(p+1)%2]. Meta uses a 3-slot ring (reuse
// distance 3). ONE __syncthreads per phase carries every dependency. All
// smem strides 68 (== 4 mod 32): A-frag LDS.32, transpose STS.32 and
// epilogue LDS.32 all bank-conflict-free. Pooling in f16 is monotone =>
// exact max semantics; adds ~1 ulp16 rounding (rel_err ~2.3e-4 expected).
template<int W, int TILE, int NSLOT>
__global__ void __launch_bounds__(512, 1) k_hmma(
    const float* __restrict__ x, const float* __restrict__ w, int colbase)
{
    constexpr int XROWS = TILE + 2;
    constexpr int XSH   = 68;              // f16x2 words per X row
    constexpr int WXS   = 68;              // f16x2 words per weight row
    constexpr int DSH   = 68;              // f16x2 words per dbuf row (64 used)
    constexpr int WW    = W * 128 * WXS;
    constexpr int XW    = XROWS * XSH;
    constexpr int DW    = TILE * DSH;
    constexpr int L     = TILE / 4;

    extern __shared__ uint32_t sm[];
    uint32_t* wsh   = sm;                        // [W][128][WXS] f16x2
    uint32_t* xbuf0 = sm + WW;
    uint32_t* xbuf1 = sm + WW + XW;
    uint32_t* dbuf0 = sm + WW + 2 * XW;
    uint32_t* dbuf1 = sm + WW + 2 * XW + DW;
    int2*     mbuf  = (int2*)(sm + WW + 2 * XW + 2 * DW);   // [3][TILE]

    const int tid  = threadIdx.x;
    const int lane = tid & 31;
    const int wid  = tid >> 5;
    const int r4   = lane >> 2;
    const int c4l  = lane & 3;
    const int grp  = wid >> 3;             // 0 or 1
    const int gwid = wid & 7;              // warp id within group
    const bool is_mma = (gwid < 2 * NSLOT);
    const int slot = gwid % NSLOT;
    const int cg   = gwid / NSLOT;
    const int rb   = slot * 32;
    const int cb   = cg * 64;
    const int cb2  = cg * 32;
    const int stid = tid & 255;            // id within group

    const int Ttot   = g_off[BATCH];
    const int ntiles = (Ttot + TILE - 1) / TILE;

    // stage weights once: global [m][c][j] f32 -> wsh[j][n][kw] f16x2
    for (int idx = tid; idx < W * 128 * 64; idx += 512) {
        int j = idx / (128 * 64);
        int r = idx - j * (128 * 64);
        int n = r >> 6, kw = r & 63;
        float f0 = w[((size_t)n * 128 + 2 * kw)     * W + j];
        float f1 = w[((size_t)n * 128 + 2 * kw + 1) * W + j];
        wsh[j * (128 * WXS) + n * WXS + kw] = pkh(f0, f1);
    }

    // stage tile t into X buffer xb + meta ring slot ms
    auto stage = [&](int t, uint32_t* xn, int ms, int id0, int nthr) {
        int base = t * TILE;
        for (int i = id0; i < XROWS * 32; i += nthr) {
            int row = i >> 5, c4 = i & 31;
            int grow = base + row;
            float4 v = make_float4(0.f, 0.f, 0.f, 0.f);
            if (grow < Ttot) v = ((const float4*)x)[(size_t)grow * 32 + c4];
            xn[row * XSH + 2 * c4]     = pkh(v.x, v.y);
            xn[row * XSH + 2 * c4 + 1] = pkh(v.z, v.w);
        }
        int2* mn = mbuf + ms * TILE;
        for (int i = id0; i < TILE; i += nthr)
            mn[i] = (base + i < Ttot) ? g_meta[base + i] : make_int2(0, -1);
    };

    // prologue: all threads stage first tile into xbuf0 / meta slot 0
    stage(blockIdx.x, xbuf0, 0, tid, 512);
    __syncthreads();

    const int K = (ntiles - 1 - (int)blockIdx.x) / gridDim.x + 1;   // my tiles

    for (int p = 0; p <= K; p++) {
        const int t_mma = blockIdx.x + p * gridDim.x;

        if ((p & 1) == grp) {
            // ---------- MMA(t_mma) + transpose ----------
            if (t_mma < ntiles && is_mma) {
                const uint32_t* xp = (p & 1) ? xbuf1 : xbuf0;
                float D[2][8][4];
#pragma unroll
                for (int mf = 0; mf < 2; mf++)
#pragma unroll
                    for (int nf = 0; nf < 8; nf++)
#pragma unroll
                        for (int q = 0; q < 4; q++) D[mf][nf][q] = 0.f;
#pragma unroll 2
                for (int kb2 = 0; kb2 < 64; kb2 += 8) {
                    uint32_t A[2][W][4];
#pragma unroll
                    for (int mf = 0; mf < 2; mf++)
#pragma unroll
                        for (int j = 0; j < W; j++) {
                            const uint32_t* pp = xp + (rb + mf * 16 + j + r4) * XSH + kb2 + c4l;
                            A[mf][j][0] = pp[0];
                            A[mf][j][1] = pp[8 * XSH];
                            A[mf][j][2] = pp[4];
                            A[mf][j][3] = pp[8 * XSH + 4];
                        }
#pragma unroll
                    for (int j = 0; j < W; j++)
#pragma unroll
                        for (int nf = 0; nf < 8; nf++) {
                            const uint32_t* q = wsh + j * (128 * WXS)
                                              + (cb + nf * 8 + r4) * WXS + kb2 + c4l;
                            uint32_t b0 = q[0], b1 = q[4];
                            mma16(D[0][nf], A[0][j], b0, b1);
                            mma16(D[1][nf], A[1][j], b0, b1);
                        }
                }
                // transpose -> dbuf[p&1] as packed f16x2 (conflict-free STS.32)
                uint32_t* dbn = (p & 1) ? dbuf1 : dbuf0;
#pragma unroll
                for (int mf = 0; mf < 2; mf++)
#pragma unroll
                    for (int nf = 0; nf < 8; nf++) {
                        int tok = rb + mf * 16 + r4;
                        int w2i = cb2 + nf * 4 + c4l;
                        dbn[tok * DSH + w2i]       = pkh(D[mf][nf][0], D[mf][nf][1]);
                        dbn[(tok + 8) * DSH + w2i] = pkh(D[mf][nf][2], D[mf][nf][3]);
                    }
            }
        } else {
            // ---------- epilogue(t_mma - grid) ----------
            if (p >= 1) {
                int t_epi = t_mma - gridDim.x;
                if (t_epi < ntiles) {
                    const uint32_t* dbn = ((p - 1) & 1) ? dbuf1 : dbuf0;
                    const int2* meta_s = mbuf + ((p - 1) % 3) * TILE;
                    const int ebase = t_epi * TILE;
                    const int ch2 = stid & 63;
                    const int t0 = (stid >> 6) * L;
                    int cur_seg = meta_s[t0].x;
                    uint32_t cm2 = 0xFC00FC00u;   // (-inf, -inf)
                    bool any = false;
#pragma unroll 4
                    for (int t = t0; t < t0 + L; t++) {
                        int2 md = meta_s[t];
                        if (md.x != cur_seg) {
                            if (any) {
                                float2 f = h2f2(cm2);
                                atomicMax(&g_Pi[(size_t)cur_seg * 384 + colbase + 2 * ch2], fkey(f.x));
                                atomicMax(&g_Pi[(size_t)cur_seg * 384 + colbase + 2 * ch2 + 1], fkey(f.y));
                            }
                            cur_seg = md.x; cm2 = 0xFC00FC00u; any = false;
                        }
                        if (ebase + t + (W - 1) < md.y) {
                            cm2 = hmax2(cm2, dbn[t * DSH + ch2]);
                            any = true;
                        }
                    }
                    if (any) {
                        float2 f = h2f2(cm2);
                        atomicMax(&g_Pi[(size_t)cur_seg * 384 + colbase + 2 * ch2], fkey(f.x));
                        atomicMax(&g_Pi[(size_t)cur_seg * 384 + colbase + 2 * ch2 + 1], fkey(f.y));
                    }
                }
            }
            // ---------- stage(t_mma + grid) ----------
            {
                int ts = t_mma + gridDim.x;
                if (ts < ntiles)
                    stage(ts, ((p + 1) & 1) ? xbuf1 : xbuf0, (p + 1) % 3, stid, 256);
            }
        }
        __syncthreads();   // single phase barrier: carries all dependencies
    }
}

// ---------------- linear + tanh (decodes pooled maxes, applies bias+relu) ----
__global__ void __launch_bounds__(256, 4) k_lin(
    const float* __restrict__ lw, const float* __restrict__ lb,
    const float* __restrict__ b0, const float* __restrict__ b1,
    const float* __restrict__ b2, float* __restrict__ out)
{
    extern __shared__ float psT[];   // [384][36]
    int tid = threadIdx.x;
    int i0  = blockIdx.x * 32;

    for (int idx = tid; idx < 32 * 384; idx += 256) {
        int i = idx / 384, k = idx - i * 384;
        float bias = (k < 128) ? b0[k] : (k < 256) ? b1[k - 128] : b2[k - 256];
        float f = fdec(g_Pi[(size_t)(i0 + i) * 384 + k]);
        psT[k * 36 + i] = fmaxf(f + bias, 0.f);
    }
    __syncthreads();

    int n  = tid & 63;
    int tg = tid >> 6;
    ull acc[2][4];
#pragma unroll
    for (int h = 0; h < 2; h++)
#pragma unroll
        for (int p = 0; p < 4; p++) acc[h][p] = 0ull;

    const float4* lwa = (const float4*)(lw + (size_t)n * 384);
    const float4* lwb = (const float4*)(lw + (size_t)(n + 64) * 384);
    const float* pbase = psT + tg * 8;

#pragma unroll 2
    for (int k4 = 0; k4 < 96; k4++) {
        float4 wa = __ldg(lwa + k4);
        float4 wb = __ldg(lwb + k4);
        float was[4] = {wa.x, wa.y, wa.z, wa.w};
        float wbs[4] = {wb.x, wb.y, wb.z, wb.w};
#pragma unroll
        for (int q = 0; q < 4; q++) {
            int k = k4 * 4 + q;
            const ulonglong2* pr = (const ulonglong2*)(pbase + k * 36);
            ulonglong2 p01 = pr[0];
            ulonglong2 p23 = pr[1];
            ull wpa, wpb;
            asm("mov.b64 %0, {%1, %1};" : "=l"(wpa) : "f"(was[q]));
            asm("mov.b64 %0, {%1, %1};" : "=l"(wpb) : "f"(wbs[q]));
            fma2(acc[0][0], p01.x, wpa); fma2(acc[1][0], p01.x, wpb);
            fma2(acc[0][1], p01.y, wpa); fma2(acc[1][1], p01.y, wpb);
            fma2(acc[0][2], p23.x, wpa); fma2(acc[1][2], p23.x, wpb);
            fma2(acc[0][3], p23.y, wpa); fma2(acc[1][3], p23.y, wpb);
        }
    }

    float biasa = lb[n], biasb = lb[n + 64];
#pragma unroll
    for (int p = 0; p < 4; p++) {
        F2U ua, ub; ua.u = acc[0][p]; ub.u = acc[1][p];
        int ra = i0 + tg * 8 + 2 * p;
        out[(size_t)ra       * 128 + n]      = tanhf(ua.f.x + biasa);
        out[(size_t)(ra + 1) * 128 + n]      = tanhf(ua.f.y + biasa);
        out[(size_t)ra       * 128 + n + 64] = tanhf(ub.f.x + biasb);
        out[(size_t)(ra + 1) * 128 + n + 64] = tanhf(ub.f.y + biasb);
    }
}

// ---------------- launch ----------------
extern "C" void kernel_launch(void* const* d_in, const int* in_sizes, int n_in,
                              void* d_out, int out_size) {
    const float* x     = (const float*)d_in[0];
    const int*   sizes = (const int*)  d_in[1];
    const float* w0    = (const float*)d_in[2];
    const float* b0    = (const float*)d_in[3];
    const float* w1    = (const float*)d_in[4];
    const float* b1    = (const float*)d_in[5];
    const float* w2    = (const float*)d_in[6];
    const float* b2    = (const float*)d_in[7];
    const float* lw    = (const float*)d_in[8];
    const float* lb    = (const float*)d_in[9];
    float* out = (float*)d_out;

    // smem words: WW + 2*XW + 2*DW + 3*TILE*2
    const int SM1 = (1 * 128 * 68 + 2 * 130 * 68 + 2 * 128 * 68 + 3 * 128 * 2) * 4;  // 178,240
    const int SM2 = (2 * 128 * 68 + 2 * 130 * 68 + 2 * 128 * 68 + 3 * 128 * 2) * 4;  // 213,056
    const int SM3 = (3 * 128 * 68 + 2 * 98 * 68 + 2 * 96 * 68 + 3 * 96 * 2) * 4;     // 212,288
    const int SML = 384 * 36 * 4;                                                    // 55,296

    cudaFuncSetAttribute((const void*)k_hmma<1, 128, 4>, cudaFuncAttributeMaxDynamicSharedMemorySize, SM1);
    cudaFuncSetAttribute((const void*)k_hmma<2, 128, 4>, cudaFuncAttributeMaxDynamicSharedMemorySize, SM2);
    cudaFuncSetAttribute((const void*)k_hmma<3, 96, 3>,  cudaFuncAttributeMaxDynamicSharedMemorySize, SM3);
    cudaFuncSetAttribute((const void*)k_lin, cudaFuncAttributeMaxDynamicSharedMemorySize, SML);

    k_init<<<(BATCH * 384 + 1023) / 1024, 1024>>>();
    k_scan<<<1, 1024>>>(sizes);
    k_prep<<<BATCH / 256, 256>>>();

    k_hmma<1, 128, 4><<<148, 512, SM1>>>(x, w0, 0);
    k_hmma<2, 128, 4><<<148, 512, SM2>>>(x, w1, 128);
    k_hmma<3, 96, 3> <<<148, 512, SM3>>>(x, w2, 256);

    k_lin<<<BATCH / 32, 256, SML>>>(lw, lb, b0, b1, b2, out);
}

// round 17
// speedup vs baseline: 1.0602x; 1.0602x over previous
#include <cuda_runtime.h>
#include <cuda_fp16.h>
#include <cstdint>

#define BATCH 8192
#define TMAX  (BATCH * 63)
typedef unsigned long long ull;

__device__ int      g_off[BATCH + 1];
__device__ unsigned g_Pi[BATCH * 384];            // ordered-uint per-(seg,col) max
__device__ __align__(16) int2 g_meta[TMAX];       // per token: {segment id, segment end}

union F2U { ull u; float2 f; };
__device__ __forceinline__ void fma2(ull& a, ull x, ull w) {
    asm("fma.rn.f32x2 %0, %1, %2, %0;" : "+l"(a) : "l"(x), "l"(w));
}
__device__ __forceinline__ unsigned fkey(float f) {
    unsigned b = __float_as_uint(f);
    return (b & 0x80000000u) ? ~b : (b | 0x80000000u);
}
__device__ __forceinline__ float fdec(unsigned k) {
    unsigned b = (k & 0x80000000u) ? (k ^ 0x80000000u) : ~k;
    return __uint_as_float(b);
}
// pack two f32 -> f16x2 (lo = first element)
__device__ __forceinline__ uint32_t pkh(float lo, float hi) {
    uint32_t r;
    asm("cvt.rn.f16x2.f32 %0, %1, %2;" : "=r"(r) : "f"(hi), "f"(lo));
    return r;
}
__device__ __forceinline__ uint32_t hmax2(uint32_t a, uint32_t b) {
    uint32_t r; asm("max.f16x2 %0, %1, %2;" : "=r"(r) : "r"(a), "r"(b)); return r;
}
__device__ __forceinline__ float2 h2f2(uint32_t v) {
    __half2 h = *reinterpret_cast<__half2*>(&v);
    return __half22float2(h);
}
// m16n8k16 fp16 HMMA, fp32 accumulate (sm_80+ baseline PTX)
__device__ __forceinline__ void mma16(float* d, const uint32_t* a, uint32_t b0, uint32_t b1) {
    asm volatile(
        "mma.sync.aligned.m16n8k16.row.col.f32.f16.f16.f32 "
        "{%0,%1,%2,%3}, {%4,%5,%6,%7}, {%8,%9}, {%0,%1,%2,%3};"
        : "+f"(d[0]), "+f"(d[1]), "+f"(d[2]), "+f"(d[3])
        : "r"(a[0]), "r"(a[1]), "r"(a[2]), "r"(a[3]), "r"(b0), "r"(b1));
}

// ---------------- small setup kernels ----------------
__global__ void k_init() {
    int i = blockIdx.x * blockDim.x + threadIdx.x;
    if (i < BATCH * 384) g_Pi[i] = 0u;
}
__global__ void k_scan(const int* __restrict__ sizes) {
    __shared__ int part[1024];
    int tid = threadIdx.x;
    int base = tid * 8;
    int pref[8];
    int s = 0;
#pragma unroll
    for (int r = 0; r < 8; r++) { pref[r] = s; s += sizes[base + r]; }
    part[tid] = s;
    __syncthreads();
    for (int off = 1; off < 1024; off <<= 1) {
        int v = (tid >= off) ? part[tid - off] : 0;
        __syncthreads();
        part[tid] += v;
        __syncthreads();
    }
    int excl = (tid > 0) ? part[tid - 1] : 0;
#pragma unroll
    for (int r = 0; r < 8; r++) g_off[base + r] = excl + pref[r];
    if (tid == 1023) g_off[BATCH] = part[1023];
}
__global__ void k_prep() {
    int s = blockIdx.x * blockDim.x + threadIdx.x;
    if (s >= BATCH) return;
    int a = g_off[s], e = g_off[s + 1];
    int2 v = make_int2(s, e);
    for (int r = a; r < e; r++) g_meta[r] = v;
}

// ---------------- fp16 HMMA conv, 2 CTAs/SM hardware overlap ----------------
// Dense stream, tap shift folded into the GEMM (A-frag row t+j accumulates
// into the same fp32 D frag). 256-thread CTAs at 2 CTAs/SM: each CTA runs the
// simple serialized stage -> MMA -> transpose -> epilogue loop; the OTHER
// resident CTA's MMA hides this CTA's memory/barrier phases (hardware
// interleaving instead of software pipelining, which rounds 13-15 showed
// doesn't pay at 1 CTA/SM). X staged as packed f16x2 (XSH=68, conflict-free
// LDS.32 A-frags); dbuf (packed f16x2, monotone f16 pooling) aliases the X
// buffer. 8 warps = 4 slots x 2 cgs, MF=2/NF per warp. CSPLIT=2 (w3) splits
// channels across CTA pairs by blockIdx parity (X re-read hits L2).
template<int W, int NCH, int CSPLIT>
__global__ void __launch_bounds__(256, 2) k_hmma(
    const float* __restrict__ x, const float* __restrict__ w, int colbase)
{
    constexpr int TILE  = 128;
    constexpr int XROWS = TILE + 2;
    constexpr int XSH   = 68;              // f16x2 words per X row
    constexpr int WXS   = 68;              // f16x2 words per weight row
    constexpr int NF    = NCH / 16;        // N-frags per warp (per cg)
    constexpr int DSH   = NCH / 2 + 4;     // f16x2 words per dbuf row
    constexpr int WW    = W * NCH * WXS;
    constexpr int XW    = XROWS * XSH;     // >= TILE*DSH (dbuf fits aliased)
    constexpr int NC2   = NCH / 2;         // f16x2 columns in epilogue
    constexpr int L     = TILE / (256 / NC2);

    extern __shared__ uint32_t sm[];
    uint32_t* wsh  = sm;                   // [W][NCH][WXS] f16x2
    uint32_t* xbuf = sm + WW;              // X f16x2 / aliased dbuf
    int2*     meta = (int2*)(sm + WW + XW);  // [TILE]

    const int tid  = threadIdx.x;
    const int lane = tid & 31;
    const int wid  = tid >> 5;
    const int r4   = lane >> 2;
    const int c4l  = lane & 3;
    const int slot = wid & 3;
    const int cg   = wid >> 2;
    const int rb   = slot * 32;
    const int cb   = cg * (NF * 8);

    int mbase, t0, tstride;
    if (CSPLIT == 2) {
        mbase   = (blockIdx.x & 1) * NCH;
        t0      = blockIdx.x >> 1;
        tstride = gridDim.x >> 1;
    } else {
        mbase   = 0;
        t0      = blockIdx.x;
        tstride = gridDim.x;
    }

    const int Ttot   = g_off[BATCH];
    const int ntiles = (Ttot + TILE - 1) / TILE;

    // stage weights once: global [m][c][j] f32 -> wsh[j][n][kw] f16x2
    for (int idx = tid; idx < W * NCH * 64; idx += 256) {
        int j = idx / (NCH * 64);
        int r = idx - j * (NCH * 64);
        int n = r >> 6, kw = r & 63;
        float f0 = w[((size_t)(mbase + n) * 128 + 2 * kw)     * W + j];
        float f1 = w[((size_t)(mbase + n) * 128 + 2 * kw + 1) * W + j];
        wsh[j * (NCH * WXS) + n * WXS + kw] = pkh(f0, f1);
    }

    for (int tile = t0; tile < ntiles; tile += tstride) {
        const int base = tile * TILE;
        __syncthreads();   // previous epilogue reads done; xbuf reusable

        // ---- stage X (f32 LDG -> f16x2 STS) + meta ----
        for (int i = tid; i < XROWS * 32; i += 256) {
            int row = i >> 5, c4 = i & 31;
            int grow = base + row;
            float4 v = make_float4(0.f, 0.f, 0.f, 0.f);
            if (grow < Ttot) v = ((const float4*)x)[(size_t)grow * 32 + c4];
            xbuf[row * XSH + 2 * c4]     = pkh(v.x, v.y);
            xbuf[row * XSH + 2 * c4 + 1] = pkh(v.z, v.w);
        }
        for (int i = tid; i < TILE; i += 256)
            meta[i] = (base + i < Ttot) ? g_meta[base + i] : make_int2(0, -1);
        __syncthreads();

        // ---- MMA (all 8 warps) ----
        float D[2][NF][4];
#pragma unroll
        for (int mf = 0; mf < 2; mf++)
#pragma unroll
            for (int nf = 0; nf < NF; nf++)
#pragma unroll
                for (int q = 0; q < 4; q++) D[mf][nf][q] = 0.f;
#pragma unroll 2
        for (int kb2 = 0; kb2 < 64; kb2 += 8) {
            uint32_t A[2][W][4];
#pragma unroll
            for (int mf = 0; mf < 2; mf++)
#pragma unroll
                for (int j = 0; j < W; j++) {
                    const uint32_t* pp = xbuf + (rb + mf * 16 + j + r4) * XSH + kb2 + c4l;
                    A[mf][j][0] = pp[0];
                    A[mf][j][1] = pp[8 * XSH];
                    A[mf][j][2] = pp[4];
                    A[mf][j][3] = pp[8 * XSH + 4];
                }
#pragma unroll
            for (int j = 0; j < W; j++)
#pragma unroll
                for (int nf = 0; nf < NF; nf++) {
                    const uint32_t* q = wsh + j * (NCH * WXS)
                                      + (cb + nf * 8 + r4) * WXS + kb2 + c4l;
                    uint32_t b0 = q[0], b1 = q[4];
                    mma16(D[0][nf], A[0][j], b0, b1);
                    mma16(D[1][nf], A[1][j], b0, b1);
                }
        }
        __syncthreads();   // xbuf reads done -> reuse as dbuf

        // ---- transpose D -> dbuf [tok][DSH] packed f16x2 ----
        {
            uint32_t* dbn = xbuf;
#pragma unroll
            for (int mf = 0; mf < 2; mf++)
#pragma unroll
                for (int nf = 0; nf < NF; nf++) {
                    int tok = rb + mf * 16 + r4;
                    int w2i = cg * (NF * 4) + nf * 4 + c4l;
                    dbn[tok * DSH + w2i]       = pkh(D[mf][nf][0], D[mf][nf][1]);
                    dbn[(tok + 8) * DSH + w2i] = pkh(D[mf][nf][2], D[mf][nf][3]);
                }
        }
        __syncthreads();

        // ---- segmented max per f16x2 channel column ----
        {
            const uint32_t* dbn = xbuf;
            const int ch2 = tid & (NC2 - 1);
            const int te0 = (tid / NC2) * L;
            int cur_seg = meta[te0].x;
            uint32_t cm2 = 0xFC00FC00u;   // (-inf, -inf)
            bool any = false;
#pragma unroll 4
            for (int t = te0; t < te0 + L; t++) {
                int2 md = meta[t];
                if (md.x != cur_seg) {
                    if (any) {
                        float2 f = h2f2(cm2);
                        atomicMax(&g_Pi[(size_t)cur_seg * 384 + colbase + mbase + 2 * ch2], fkey(f.x));
                        atomicMax(&g_Pi[(size_t)cur_seg * 384 + colbase + mbase + 2 * ch2 + 1], fkey(f.y));
                    }
                    cur_seg = md.x; cm2 = 0xFC00FC00u; any = false;
                }
                if (base + t + (W - 1) < md.y) {
                    cm2 = hmax2(cm2, dbn[t * DSH + ch2]);
                    any = true;
                }
            }
            if (any) {
                float2 f = h2f2(cm2);
                atomicMax(&g_Pi[(size_t)cur_seg * 384 + colbase + mbase + 2 * ch2], fkey(f.x));
                atomicMax(&g_Pi[(size_t)cur_seg * 384 + colbase + mbase + 2 * ch2 + 1], fkey(f.y));
            }
        }
    }
}

// ---------------- linear + tanh (decodes pooled maxes, applies bias+relu) ----
__global__ void __launch_bounds__(256, 4) k_lin(
    const float* __restrict__ lw, const float* __restrict__ lb,
    const float* __restrict__ b0, const float* __restrict__ b1,
    const float* __restrict__ b2, float* __restrict__ out)
{
    extern __shared__ float psT[];   // [384][36]
    int tid = threadIdx.x;
    int i0  = blockIdx.x * 32;

    for (int idx = tid; idx < 32 * 384; idx += 256) {
        int i = idx / 384, k = idx - i * 384;
        float bias = (k < 128) ? b0[k] : (k < 256) ? b1[k - 128] : b2[k - 256];
        float f = fdec(g_Pi[(size_t)(i0 + i) * 384 + k]);
        psT[k * 36 + i] = fmaxf(f + bias, 0.f);
    }
    __syncthreads();

    int n  = tid & 63;
    int tg = tid >> 6;
    ull acc[2][4];
#pragma unroll
    for (int h = 0; h < 2; h++)
#pragma unroll
        for (int p = 0; p < 4; p++) acc[h][p] = 0ull;

    const float4* lwa = (const float4*)(lw + (size_t)n * 384);
    const float4* lwb = (const float4*)(lw + (size_t)(n + 64) * 384);
    const float* pbase = psT + tg * 8;

#pragma unroll 2
    for (int k4 = 0; k4 < 96; k4++) {
        float4 wa = __ldg(lwa + k4);
        float4 wb = __ldg(lwb + k4);
        float was[4] = {wa.x, wa.y, wa.z, wa.w};
        float wbs[4] = {wb.x, wb.y, wb.z, wb.w};
#pragma unroll
        for (int q = 0; q < 4; q++) {
            int k = k4 * 4 + q;
            const ulonglong2* pr = (const ulonglong2*)(pbase + k * 36);
            ulonglong2 p01 = pr[0];
            ulonglong2 p23 = pr[1];
            ull wpa, wpb;
            asm("mov.b64 %0, {%1, %1};" : "=l"(wpa) : "f"(was[q]));
            asm("mov.b64 %0, {%1, %1};" : "=l"(wpb) : "f"(wbs[q]));
            fma2(acc[0][0], p01.x, wpa); fma2(acc[1][0], p01.x, wpb);
            fma2(acc[0][1], p01.y, wpa); fma2(acc[1][1], p01.y, wpb);
            fma2(acc[0][2], p23.x, wpa); fma2(acc[1][2], p23.x, wpb);
            fma2(acc[0][3], p23.y, wpa); fma2(acc[1][3], p23.y, wpb);
        }
    }

    float biasa = lb[n], biasb = lb[n + 64];
#pragma unroll
    for (int p = 0; p < 4; p++) {
        F2U ua, ub; ua.u = acc[0][p]; ub.u = acc[1][p];
        int ra = i0 + tg * 8 + 2 * p;
        out[(size_t)ra       * 128 + n]      = tanhf(ua.f.x + biasa);
        out[(size_t)(ra + 1) * 128 + n]      = tanhf(ua.f.y + biasa);
        out[(size_t)ra       * 128 + n + 64] = tanhf(ub.f.x + biasb);
        out[(size_t)(ra + 1) * 128 + n + 64] = tanhf(ub.f.y + biasb);
    }
}

// ---------------- launch ----------------
extern "C" void kernel_launch(void* const* d_in, const int* in_sizes, int n_in,
                              void* d_out, int out_size) {
    const float* x     = (const float*)d_in[0];
    const int*   sizes = (const int*)  d_in[1];
    const float* w0    = (const float*)d_in[2];
    const float* b0    = (const float*)d_in[3];
    const float* w1    = (const float*)d_in[4];
    const float* b1    = (const float*)d_in[5];
    const float* w2    = (const float*)d_in[6];
    const float* b2    = (const float*)d_in[7];
    const float* lw    = (const float*)d_in[8];
    const float* lb    = (const float*)d_in[9];
    float* out = (float*)d_out;

    // smem (bytes): (WW + XW)*4 + TILE*8   (2 CTAs/SM: all <= ~113KB)
    const int SM1 = (1 * 128 * 68 + 130 * 68) * 4 + 128 * 8;  //  71,200
    const int SM2 = (2 * 128 * 68 + 130 * 68) * 4 + 128 * 8;  // 106,016
    const int SM3 = (3 * 64 * 68 + 130 * 68) * 4 + 128 * 8;   //  88,608
    const int SML = 384 * 36 * 4;                              //  55,296

    cudaFuncSetAttribute((const void*)k_hmma<1, 128, 1>, cudaFuncAttributeMaxDynamicSharedMemorySize, SM1);
    cudaFuncSetAttribute((const void*)k_hmma<2, 128, 1>, cudaFuncAttributeMaxDynamicSharedMemorySize, SM2);
    cudaFuncSetAttribute((const void*)k_hmma<3, 64, 2>,  cudaFuncAttributeMaxDynamicSharedMemorySize, SM3);
    cudaFuncSetAttribute((const void*)k_lin, cudaFuncAttributeMaxDynamicSharedMemorySize, SML);

    k_init<<<(BATCH * 384 + 1023) / 1024, 1024>>>();
    k_scan<<<1, 1024>>>(sizes);
    k_prep<<<BATCH / 256, 256>>>();

    k_hmma<1, 128, 1><<<296, 256, SM1>>>(x, w0, 0);
    k_hmma<2, 128, 1><<<296, 256, SM2>>>(x, w1, 128);
    k_hmma<3, 64, 2> <<<296, 256, SM3>>>(x, w2, 256);

    k_lin<<<BATCH / 32, 256, SML>>>(lw, lb, b0, b1, b2, out);
}